// round 2
// baseline (speedup 1.0000x reference)
#include <cuda_runtime.h>
#include <math.h>

#define TOT     128000
#define HDIM    64
#define NHEADS  4
#define DHEAD   16
#define FIN     32
#define NEDGE   512000
#define NB      128
#define OBSD    1500
#define HSD     512
#define NOUTD   15
#define VHD     128
#define NA      15
#define NLAYER  4

// ---------------- scratch (device globals; no allocation allowed) ----------------
__device__ __align__(16) float g_x[TOT * HDIM];
__device__ __align__(16) float g_q[TOT * HDIM];
__device__ __align__(16) float g_k[TOT * HDIM];
__device__ __align__(16) float g_v[TOT * HDIM];
__device__ __align__(16) float g_buf[TOT * HDIM];    // attention aggregate
__device__ __align__(16) float g_buf2[TOT * HDIM];   // gemm epilogue scratch
__device__ __align__(16) float g_hid[TOT * 2 * HDIM];// FFN hidden
__device__ int g_counts[TOT];
__device__ int g_fill[TOT];
__device__ int g_rowptr[TOT + 1];
__device__ int g_csrc[NEDGE];
__device__ __align__(16) float g_gat[NB * NA];
__device__ __align__(16) float g_feat[NB * HSD];
__device__ __align__(16) float g_feat2[NB * HSD];
__device__ __align__(16) float g_vh[NB * VHD];
__device__ __align__(16) float g_vh2[NB * VHD];

// ---------------- CSR build ----------------
__global__ void zero_counts_kernel() {
    int i = blockIdx.x * blockDim.x + threadIdx.x;
    if (i < TOT) { g_counts[i] = 0; g_fill[i] = 0; }
}

__global__ void count_edges_kernel(const int* __restrict__ edge_dst) {
    int e = blockIdx.x * blockDim.x + threadIdx.x;
    if (e < NEDGE) atomicAdd(&g_counts[edge_dst[e]], 1);
}

// single-block exclusive scan over g_counts -> g_rowptr (TOT = 125 * 1024 exactly)
__global__ void scan_kernel() {
    __shared__ int wsum[32];
    __shared__ int carry;
    int tid = threadIdx.x;
    int lane = tid & 31, wid = tid >> 5;
    if (tid == 0) carry = 0;
    __syncthreads();
    for (int base = 0; base < TOT; base += 1024) {
        int i = base + tid;
        int val = (i < TOT) ? g_counts[i] : 0;
        int s = val;
        #pragma unroll
        for (int off = 1; off < 32; off <<= 1) {
            int t = __shfl_up_sync(0xffffffffu, s, off);
            if (lane >= off) s += t;
        }
        if (lane == 31) wsum[wid] = s;
        __syncthreads();
        if (wid == 0) {
            int ws = wsum[lane];
            #pragma unroll
            for (int off = 1; off < 32; off <<= 1) {
                int t = __shfl_up_sync(0xffffffffu, ws, off);
                if (lane >= off) ws += t;
            }
            wsum[lane] = ws;  // inclusive over warp sums
        }
        __syncthreads();
        int pre = (wid > 0) ? wsum[wid - 1] : 0;
        int incl = pre + s;
        if (i < TOT) g_rowptr[i] = carry + incl - val;  // exclusive
        __syncthreads();
        if (tid == 0) carry += wsum[31];
        __syncthreads();
    }
    if (tid == 0) g_rowptr[TOT] = carry;
}

__global__ void scatter_edges_kernel(const int* __restrict__ edge_src,
                                     const int* __restrict__ edge_dst) {
    int e = blockIdx.x * blockDim.x + threadIdx.x;
    if (e < NEDGE) {
        int d = edge_dst[e];
        int pos = atomicAdd(&g_fill[d], 1);
        g_csrc[g_rowptr[d] + pos] = edge_src[e];
    }
}

// ---------------- tiled SGEMM: C[M,N] = A[M,K] @ B[K,N] (+bias)(+relu) ----------------
// BM=BN=64, BK=32. M,N multiples of 64; K multiple of 32. 256 threads, 4x4 micro-tile.
__global__ __launch_bounds__(256) void gemm64_kernel(
    const float* __restrict__ A, const float* __restrict__ B,
    const float* __restrict__ bias, float* __restrict__ C,
    int N, int K, int act)
{
    __shared__ float As[32][65];
    __shared__ float Bs[32][68];
    int bm = blockIdx.y * 64, bn = blockIdx.x * 64;
    int tid = threadIdx.x;
    int tx = tid & 15, ty = tid >> 4;
    float acc[4][4] = {};
    for (int k0 = 0; k0 < K; k0 += 32) {
        #pragma unroll
        for (int i = tid; i < 64 * 32; i += 256) {
            int c = i & 31, r = i >> 5;
            As[c][r] = A[(bm + r) * K + k0 + c];
        }
        #pragma unroll
        for (int i = tid; i < 32 * 64; i += 256) {
            int c = i & 63, r = i >> 6;
            Bs[r][c] = B[(k0 + r) * N + bn + c];
        }
        __syncthreads();
        #pragma unroll
        for (int kk = 0; kk < 32; kk++) {
            float a0 = As[kk][ty * 4 + 0], a1 = As[kk][ty * 4 + 1];
            float a2 = As[kk][ty * 4 + 2], a3 = As[kk][ty * 4 + 3];
            float b0 = Bs[kk][tx * 4 + 0], b1 = Bs[kk][tx * 4 + 1];
            float b2 = Bs[kk][tx * 4 + 2], b3 = Bs[kk][tx * 4 + 3];
            acc[0][0] += a0 * b0; acc[0][1] += a0 * b1; acc[0][2] += a0 * b2; acc[0][3] += a0 * b3;
            acc[1][0] += a1 * b0; acc[1][1] += a1 * b1; acc[1][2] += a1 * b2; acc[1][3] += a1 * b3;
            acc[2][0] += a2 * b0; acc[2][1] += a2 * b1; acc[2][2] += a2 * b2; acc[2][3] += a2 * b3;
            acc[3][0] += a3 * b0; acc[3][1] += a3 * b1; acc[3][2] += a3 * b2; acc[3][3] += a3 * b3;
        }
        __syncthreads();
    }
    #pragma unroll
    for (int i = 0; i < 4; i++) {
        int row = bm + ty * 4 + i;
        #pragma unroll
        for (int j = 0; j < 4; j++) {
            int col = bn + tx * 4 + j;
            float vv = acc[i][j];
            if (bias) vv += bias[col];
            if (act) vv = fmaxf(vv, 0.0f);
            C[row * N + col] = vv;
        }
    }
}

// ---------------- GAT attention: one warp per destination node ----------------
__global__ __launch_bounds__(256) void gat_attn_kernel() {
    int warp = (blockIdx.x * blockDim.x + threadIdx.x) >> 5;
    int lane = threadIdx.x & 31;
    if (warp >= TOT) return;
    int node = warp;
    int beg = g_rowptr[node], end = g_rowptr[node + 1];
    const float2* q2 = (const float2*)g_q;
    const float2* k2 = (const float2*)g_k;
    const float2* v2 = (const float2*)g_v;
    float2 qv = q2[node * 32 + lane];
    const float scale = 0.25f;  // 1/sqrt(16)
    // pass 1: per-head max
    float mh = -INFINITY;
    for (int e = beg; e < end; e++) {
        int s = g_csrc[e];
        float2 kv = k2[s * 32 + lane];
        float d = qv.x * kv.x + qv.y * kv.y;
        d += __shfl_xor_sync(0xffffffffu, d, 1);
        d += __shfl_xor_sync(0xffffffffu, d, 2);
        d += __shfl_xor_sync(0xffffffffu, d, 4);
        d *= scale;
        mh = fmaxf(mh, d);
    }
    // pass 2: exp-sum and weighted aggregate
    float denom = 0.0f, acc0 = 0.0f, acc1 = 0.0f;
    for (int e = beg; e < end; e++) {
        int s = g_csrc[e];
        float2 kv = k2[s * 32 + lane];
        float d = qv.x * kv.x + qv.y * kv.y;
        d += __shfl_xor_sync(0xffffffffu, d, 1);
        d += __shfl_xor_sync(0xffffffffu, d, 2);
        d += __shfl_xor_sync(0xffffffffu, d, 4);
        d *= scale;
        float w = __expf(d - mh);
        denom += w;
        float2 vv = v2[s * 32 + lane];
        acc0 += w * vv.x;
        acc1 += w * vv.y;
    }
    float invd = 1.0f / (denom + 1e-9f);
    float2 o; o.x = acc0 * invd; o.y = acc1 * invd;
    ((float2*)g_buf)[node * 32 + lane] = o;
}

// ---------------- residual + LayerNorm (in-place on g_x), warp per row ----------------
__global__ __launch_bounds__(256) void resid_ln_kernel(
    const float* __restrict__ res, const float* __restrict__ g, const float* __restrict__ b)
{
    int row = (blockIdx.x * blockDim.x + threadIdx.x) >> 5;
    int lane = threadIdx.x & 31;
    if (row >= TOT) return;
    float2 xv = ((const float2*)g_x)[row * 32 + lane];
    float2 rv = ((const float2*)res)[row * 32 + lane];
    float v0 = xv.x + rv.x, v1 = xv.y + rv.y;
    float s = v0 + v1;
    #pragma unroll
    for (int off = 16; off >= 1; off >>= 1) s += __shfl_xor_sync(0xffffffffu, s, off);
    float mean = s * (1.0f / 64.0f);
    float d0 = v0 - mean, d1 = v1 - mean;
    float var = d0 * d0 + d1 * d1;
    #pragma unroll
    for (int off = 16; off >= 1; off >>= 1) var += __shfl_xor_sync(0xffffffffu, var, off);
    float rs = rsqrtf(var * (1.0f / 64.0f) + 1e-5f);
    float2 gg = ((const float2*)g)[lane];
    float2 bb = ((const float2*)b)[lane];
    float2 o; o.x = d0 * rs * gg.x + bb.x; o.y = d1 * rs * gg.y + bb.y;
    ((float2*)g_x)[row * 32 + lane] = o;
}

// ---------------- readout: gat_out = x[agent_nodes] @ Wr + br ----------------
__global__ void readout_kernel(const int* __restrict__ agent_nodes,
                               const float* __restrict__ Wr, const float* __restrict__ br)
{
    int i = blockIdx.x * blockDim.x + threadIdx.x;
    if (i >= NB * NA) return;
    int bi = i / NA, a = i % NA;
    int node = agent_nodes[bi];
    float s = br[a];
    #pragma unroll
    for (int h = 0; h < HDIM; h++) s += g_x[node * HDIM + h] * Wr[h * NA + a];
    g_gat[i] = s;
}

// ---------------- FC: block per batch row, input row in smem ----------------
__global__ __launch_bounds__(256) void fc_kernel(
    const float* __restrict__ A, const float* __restrict__ W,
    const float* __restrict__ bias, float* __restrict__ C,
    int in_dim, int out_dim, int act)
{
    __shared__ float srow[1536];
    int row = blockIdx.x;
    for (int i = threadIdx.x; i < in_dim; i += blockDim.x)
        srow[i] = A[row * in_dim + i];
    __syncthreads();
    for (int j = threadIdx.x; j < out_dim; j += blockDim.x) {
        float s = bias ? bias[j] : 0.0f;
        for (int k = 0; k < in_dim; k++) s += srow[k] * W[k * out_dim + j];
        if (act == 1) s = tanhf(s);
        C[row * out_dim + j] = s;
    }
}

// FC with concat([g_gat row (15), obs row (1500)]) input -> g_feat (tanh)
__global__ __launch_bounds__(256) void fc_concat_kernel(
    const float* __restrict__ obs, const float* __restrict__ W,
    const float* __restrict__ bias)
{
    __shared__ float srow[1536];
    int row = blockIdx.x;
    for (int i = threadIdx.x; i < NA; i += blockDim.x) srow[i] = g_gat[row * NA + i];
    for (int i = threadIdx.x; i < OBSD; i += blockDim.x) srow[NA + i] = obs[row * OBSD + i];
    __syncthreads();
    const int in_dim = NA + OBSD;
    for (int j = threadIdx.x; j < HSD; j += blockDim.x) {
        float s = bias[j];
        for (int k = 0; k < in_dim; k++) s += srow[k] * W[k * HSD + j];
        g_feat[row * HSD + j] = tanhf(s);
    }
}

__global__ void value_kernel(const float* __restrict__ Wvo, const float* __restrict__ bvo,
                             float* __restrict__ out)
{
    int bi = threadIdx.x;
    if (bi >= NB) return;
    float s = bvo[0];
    #pragma unroll
    for (int k = 0; k < VHD; k++) s += g_vh2[bi * VHD + k] * Wvo[k];
    out[NB * NOUTD + bi] = s;
}

// ---------------- launch ----------------
extern "C" void kernel_launch(void* const* d_in, const int* in_sizes, int n_in,
                              void* d_out, int out_size)
{
    const float* node_feats = (const float*)d_in[0];
    const float* obs        = (const float*)d_in[1];
    const int*   edge_src   = (const int*)d_in[2];
    const int*   edge_dst   = (const int*)d_in[3];
    const int*   agent_nodes= (const int*)d_in[4];
    const float* W_in = (const float*)d_in[5];
    const float* Wq   = (const float*)d_in[6];
    const float* Wk   = (const float*)d_in[7];
    const float* Wv   = (const float*)d_in[8];
    const float* Wo   = (const float*)d_in[9];
    const float* ln1g = (const float*)d_in[10];
    const float* ln1b = (const float*)d_in[11];
    const float* W1   = (const float*)d_in[12];
    const float* b1   = (const float*)d_in[13];
    const float* W2   = (const float*)d_in[14];
    const float* b2   = (const float*)d_in[15];
    const float* ln2g = (const float*)d_in[16];
    const float* ln2b = (const float*)d_in[17];
    const float* Wr   = (const float*)d_in[18];
    const float* br   = (const float*)d_in[19];
    const float* Wp1  = (const float*)d_in[20];
    const float* bp1  = (const float*)d_in[21];
    const float* Wp2  = (const float*)d_in[22];
    const float* bp2  = (const float*)d_in[23];
    const float* Wlog = (const float*)d_in[24];
    const float* blog = (const float*)d_in[25];
    const float* Wv1  = (const float*)d_in[26];
    const float* bv1  = (const float*)d_in[27];
    const float* Wv2  = (const float*)d_in[28];
    const float* bv2  = (const float*)d_in[29];
    const float* Wvo  = (const float*)d_in[30];
    const float* bvo  = (const float*)d_in[31];
    float* out = (float*)d_out;

    float *x, *q, *k, *v, *buf, *buf2, *hid, *feat, *feat2, *vh, *vh2;
    cudaGetSymbolAddress((void**)&x,    g_x);
    cudaGetSymbolAddress((void**)&q,    g_q);
    cudaGetSymbolAddress((void**)&k,    g_k);
    cudaGetSymbolAddress((void**)&v,    g_v);
    cudaGetSymbolAddress((void**)&buf,  g_buf);
    cudaGetSymbolAddress((void**)&buf2, g_buf2);
    cudaGetSymbolAddress((void**)&hid,  g_hid);
    cudaGetSymbolAddress((void**)&feat, g_feat);
    cudaGetSymbolAddress((void**)&feat2,g_feat2);
    cudaGetSymbolAddress((void**)&vh,   g_vh);
    cudaGetSymbolAddress((void**)&vh2,  g_vh2);

    const int MB = TOT / 64;  // 2000 row blocks

    // CSR build (reused by all 4 layers)
    zero_counts_kernel<<<(TOT + 255) / 256, 256>>>();
    count_edges_kernel<<<(NEDGE + 255) / 256, 256>>>(edge_dst);
    scan_kernel<<<1, 1024>>>();
    scatter_edges_kernel<<<(NEDGE + 255) / 256, 256>>>(edge_src, edge_dst);

    // input projection: x = node_feats @ W_in   [TOT,32]@[32,64]
    gemm64_kernel<<<dim3(1, MB), 256>>>(node_feats, W_in, nullptr, x, 64, 32, 0);

    for (int l = 0; l < NLAYER; l++) {
        const float* Wq_l = Wq + l * HDIM * HDIM;
        const float* Wk_l = Wk + l * HDIM * HDIM;
        const float* Wv_l = Wv + l * HDIM * HDIM;
        const float* Wo_l = Wo + l * HDIM * HDIM;
        gemm64_kernel<<<dim3(1, MB), 256>>>(x, Wq_l, nullptr, q, 64, 64, 0);
        gemm64_kernel<<<dim3(1, MB), 256>>>(x, Wk_l, nullptr, k, 64, 64, 0);
        gemm64_kernel<<<dim3(1, MB), 256>>>(x, Wv_l, nullptr, v, 64, 64, 0);
        gat_attn_kernel<<<TOT / 8, 256>>>();
        gemm64_kernel<<<dim3(1, MB), 256>>>(buf, Wo_l, nullptr, buf2, 64, 64, 0);
        resid_ln_kernel<<<TOT / 8, 256>>>(buf2, ln1g + l * HDIM, ln1b + l * HDIM);
        gemm64_kernel<<<dim3(2, MB), 256>>>(x, W1 + l * HDIM * 2 * HDIM, b1 + l * 2 * HDIM,
                                            hid, 2 * HDIM, HDIM, 1);
        gemm64_kernel<<<dim3(1, MB), 256>>>(hid, W2 + l * 2 * HDIM * HDIM, b2 + l * HDIM,
                                            buf2, HDIM, 2 * HDIM, 0);
        resid_ln_kernel<<<TOT / 8, 256>>>(buf2, ln2g + l * HDIM, ln2b + l * HDIM);
    }

    // heads
    readout_kernel<<<(NB * NA + 255) / 256, 256>>>(agent_nodes, Wr, br);
    fc_concat_kernel<<<NB, 256>>>(obs, Wp1, bp1);                       // -> g_feat (tanh)
    fc_kernel<<<NB, 256>>>(feat, Wp2, bp2, feat2, HSD, HSD, 1);         // tanh
    fc_kernel<<<NB, 256>>>(feat2, Wlog, blog, out, HSD, NOUTD, 0);      // logits -> out[0:1920]
    fc_kernel<<<NB, 256>>>(obs, Wv1, bv1, vh, OBSD, VHD, 1);            // tanh
    fc_kernel<<<NB, 256>>>(vh, Wv2, bv2, vh2, VHD, VHD, 1);             // tanh
    value_kernel<<<1, 128>>>(Wvo, bvo, out);                            // value -> out[1920:2048]
}

// round 4
// speedup vs baseline: 1.6190x; 1.6190x over previous
#include <cuda_runtime.h>
#include <math.h>

#define TOT     128000
#define HDIM    64
#define NHEADS  4
#define DHEAD   16
#define FIN     32
#define NEDGE   512000
#define NB      128
#define OBSD    1500
#define HSD     512
#define NOUTD   15
#define VHD     128
#define NA      15
#define NLAYER  4

// ---------------- scratch (device globals; no allocation allowed) ----------------
__device__ __align__(16) float g_x[TOT * HDIM];
__device__ __align__(16) float g_q[TOT * HDIM];
__device__ __align__(16) float g_k[TOT * HDIM];
__device__ __align__(16) float g_v[TOT * HDIM];
__device__ __align__(16) float g_buf[TOT * HDIM];    // attention aggregate
__device__ __align__(16) float g_buf2[TOT * HDIM];   // gemm epilogue scratch
__device__ __align__(16) float g_hid[TOT * 2 * HDIM];// FFN hidden
__device__ int g_counts[TOT];
__device__ int g_fill[TOT];
__device__ int g_rowptr[TOT + 1];
__device__ int g_csrc[NEDGE];
__device__ __align__(16) float g_gat[NB * NA];
__device__ __align__(16) float g_feat[NB * HSD];
__device__ __align__(16) float g_feat2[NB * HSD];
__device__ __align__(16) float g_vh[NB * VHD];
__device__ __align__(16) float g_vh2[NB * VHD];

// ---------------- CSR build ----------------
__global__ void zero_counts_kernel() {
    int i = blockIdx.x * blockDim.x + threadIdx.x;
    if (i < TOT) { g_counts[i] = 0; g_fill[i] = 0; }
}

__global__ void count_edges_kernel(const int* __restrict__ edge_dst) {
    int e = blockIdx.x * blockDim.x + threadIdx.x;
    if (e < NEDGE) atomicAdd(&g_counts[edge_dst[e]], 1);
}

__global__ void scan_kernel() {
    __shared__ int wsum[32];
    __shared__ int carry;
    int tid = threadIdx.x;
    int lane = tid & 31, wid = tid >> 5;
    if (tid == 0) carry = 0;
    __syncthreads();
    for (int base = 0; base < TOT; base += 1024) {
        int i = base + tid;
        int val = (i < TOT) ? g_counts[i] : 0;
        int s = val;
        #pragma unroll
        for (int off = 1; off < 32; off <<= 1) {
            int t = __shfl_up_sync(0xffffffffu, s, off);
            if (lane >= off) s += t;
        }
        if (lane == 31) wsum[wid] = s;
        __syncthreads();
        if (wid == 0) {
            int ws = wsum[lane];
            #pragma unroll
            for (int off = 1; off < 32; off <<= 1) {
                int t = __shfl_up_sync(0xffffffffu, ws, off);
                if (lane >= off) ws += t;
            }
            wsum[lane] = ws;
        }
        __syncthreads();
        int pre = (wid > 0) ? wsum[wid - 1] : 0;
        int incl = pre + s;
        if (i < TOT) g_rowptr[i] = carry + incl - val;
        __syncthreads();
        if (tid == 0) carry += wsum[31];
        __syncthreads();
    }
    if (tid == 0) g_rowptr[TOT] = carry;
}

__global__ void scatter_edges_kernel(const int* __restrict__ edge_src,
                                     const int* __restrict__ edge_dst) {
    int e = blockIdx.x * blockDim.x + threadIdx.x;
    if (e < NEDGE) {
        int d = edge_dst[e];
        int pos = atomicAdd(&g_fill[d], 1);
        g_csrc[g_rowptr[d] + pos] = edge_src[e];
    }
}

// ---------------- tf32 tensor-core GEMM ----------------
// C[M,N] = A[M,K] @ B[K,N] (+bias)(+relu)
// BM=128, BN=64, BK=32. 256 threads (8 warps); warp w owns rows [w*16, w*16+16).
// M % 128 == 0, N % 64 == 0, K % 32 == 0.
__device__ __forceinline__ unsigned tf32u(float x) {
    float r;
    asm("cvt.rna.tf32.f32 %0, %1;" : "=f"(r) : "f"(x));
    return __float_as_uint(r);
}

__global__ __launch_bounds__(256) void gemm_tf32_kernel(
    const float* __restrict__ A, const float* __restrict__ B,
    const float* __restrict__ bias, float* __restrict__ C,
    int N, int K, int act)
{
    __shared__ float As[128][36];   // stride 36: frag loads conflict-free (4g+t)
    __shared__ float Bs[32][72];    // stride 72: frag loads conflict-free (8t+g)
    int bm = blockIdx.y * 128, bn = blockIdx.x * 64;
    int tid = threadIdx.x;
    int warp = tid >> 5, lane = tid & 31;
    int g = lane >> 2, t = lane & 3;

    float acc[8][4];
    #pragma unroll
    for (int j = 0; j < 8; j++)
        #pragma unroll
        for (int i = 0; i < 4; i++) acc[j][i] = 0.0f;

    for (int k0 = 0; k0 < K; k0 += 32) {
        // stage A tile 128x32 (as tf32 bit patterns)
        #pragma unroll
        for (int i = 0; i < 4; i++) {
            int idx = i * 256 + tid;          // float4 index, 0..1023
            int r = idx >> 3;
            int c = (idx & 7) * 4;
            float4 v = *(const float4*)&A[(size_t)(bm + r) * K + k0 + c];
            As[r][c + 0] = __uint_as_float(tf32u(v.x));
            As[r][c + 1] = __uint_as_float(tf32u(v.y));
            As[r][c + 2] = __uint_as_float(tf32u(v.z));
            As[r][c + 3] = __uint_as_float(tf32u(v.w));
        }
        // stage B tile 32x64
        #pragma unroll
        for (int i = 0; i < 2; i++) {
            int idx = i * 256 + tid;          // float4 index, 0..511
            int r = idx >> 4;
            int c = (idx & 15) * 4;
            float4 v = *(const float4*)&B[(size_t)(k0 + r) * N + bn + c];
            Bs[r][c + 0] = __uint_as_float(tf32u(v.x));
            Bs[r][c + 1] = __uint_as_float(tf32u(v.y));
            Bs[r][c + 2] = __uint_as_float(tf32u(v.z));
            Bs[r][c + 3] = __uint_as_float(tf32u(v.w));
        }
        __syncthreads();
        #pragma unroll
        for (int ks = 0; ks < 4; ks++) {
            int kk = ks * 8;
            unsigned a0 = __float_as_uint(As[warp * 16 + g][kk + t]);
            unsigned a1 = __float_as_uint(As[warp * 16 + g + 8][kk + t]);
            unsigned a2 = __float_as_uint(As[warp * 16 + g][kk + t + 4]);
            unsigned a3 = __float_as_uint(As[warp * 16 + g + 8][kk + t + 4]);
            #pragma unroll
            for (int j = 0; j < 8; j++) {
                unsigned b0 = __float_as_uint(Bs[kk + t][j * 8 + g]);
                unsigned b1 = __float_as_uint(Bs[kk + t + 4][j * 8 + g]);
                asm volatile(
                    "mma.sync.aligned.m16n8k8.row.col.f32.tf32.tf32.f32 "
                    "{%0,%1,%2,%3}, {%4,%5,%6,%7}, {%8,%9}, {%0,%1,%2,%3};"
                    : "+f"(acc[j][0]), "+f"(acc[j][1]), "+f"(acc[j][2]), "+f"(acc[j][3])
                    : "r"(a0), "r"(a1), "r"(a2), "r"(a3), "r"(b0), "r"(b1));
            }
        }
        __syncthreads();
    }
    // epilogue: c0=(g, t*2) c1=(g, t*2+1) c2=(g+8, t*2) c3=(g+8, t*2+1) per n-tile j
    int row0 = bm + warp * 16 + g;
    #pragma unroll
    for (int j = 0; j < 8; j++) {
        int col = bn + j * 8 + t * 2;
        float v0 = acc[j][0], v1 = acc[j][1], v2 = acc[j][2], v3 = acc[j][3];
        if (bias) {
            float bb0 = bias[col], bb1 = bias[col + 1];
            v0 += bb0; v1 += bb1; v2 += bb0; v3 += bb1;
        }
        if (act) {
            v0 = fmaxf(v0, 0.0f); v1 = fmaxf(v1, 0.0f);
            v2 = fmaxf(v2, 0.0f); v3 = fmaxf(v3, 0.0f);
        }
        float2 w0; w0.x = v0; w0.y = v1;
        float2 w1; w1.x = v2; w1.y = v3;
        *(float2*)&C[(size_t)row0 * N + col] = w0;
        *(float2*)&C[(size_t)(row0 + 8) * N + col] = w1;
    }
}

// ---------------- GAT attention: one warp per destination node ----------------
__global__ __launch_bounds__(256) void gat_attn_kernel() {
    int warp = (blockIdx.x * blockDim.x + threadIdx.x) >> 5;
    int lane = threadIdx.x & 31;
    if (warp >= TOT) return;
    int node = warp;
    int beg = g_rowptr[node], end = g_rowptr[node + 1];
    const float2* q2 = (const float2*)g_q;
    const float2* k2 = (const float2*)g_k;
    const float2* v2 = (const float2*)g_v;
    float2 qv = q2[node * 32 + lane];
    const float scale = 0.25f;
    float mh = -INFINITY;
    for (int e = beg; e < end; e++) {
        int s = g_csrc[e];
        float2 kv = k2[s * 32 + lane];
        float d = qv.x * kv.x + qv.y * kv.y;
        d += __shfl_xor_sync(0xffffffffu, d, 1);
        d += __shfl_xor_sync(0xffffffffu, d, 2);
        d += __shfl_xor_sync(0xffffffffu, d, 4);
        d *= scale;
        mh = fmaxf(mh, d);
    }
    float denom = 0.0f, acc0 = 0.0f, acc1 = 0.0f;
    for (int e = beg; e < end; e++) {
        int s = g_csrc[e];
        float2 kv = k2[s * 32 + lane];
        float d = qv.x * kv.x + qv.y * kv.y;
        d += __shfl_xor_sync(0xffffffffu, d, 1);
        d += __shfl_xor_sync(0xffffffffu, d, 2);
        d += __shfl_xor_sync(0xffffffffu, d, 4);
        d *= scale;
        float w = __expf(d - mh);
        denom += w;
        float2 vv = v2[s * 32 + lane];
        acc0 += w * vv.x;
        acc1 += w * vv.y;
    }
    float invd = 1.0f / (denom + 1e-9f);
    float2 o; o.x = acc0 * invd; o.y = acc1 * invd;
    ((float2*)g_buf)[node * 32 + lane] = o;
}

// ---------------- residual + LayerNorm (in-place on g_x), warp per row ----------------
__global__ __launch_bounds__(256) void resid_ln_kernel(
    const float* __restrict__ res, const float* __restrict__ g, const float* __restrict__ b)
{
    int row = (blockIdx.x * blockDim.x + threadIdx.x) >> 5;
    int lane = threadIdx.x & 31;
    if (row >= TOT) return;
    float2 xv = ((const float2*)g_x)[row * 32 + lane];
    float2 rv = ((const float2*)res)[row * 32 + lane];
    float v0 = xv.x + rv.x, v1 = xv.y + rv.y;
    float s = v0 + v1;
    #pragma unroll
    for (int off = 16; off >= 1; off >>= 1) s += __shfl_xor_sync(0xffffffffu, s, off);
    float mean = s * (1.0f / 64.0f);
    float d0 = v0 - mean, d1 = v1 - mean;
    float var = d0 * d0 + d1 * d1;
    #pragma unroll
    for (int off = 16; off >= 1; off >>= 1) var += __shfl_xor_sync(0xffffffffu, var, off);
    float rs = rsqrtf(var * (1.0f / 64.0f) + 1e-5f);
    float2 gg = ((const float2*)g)[lane];
    float2 bb = ((const float2*)b)[lane];
    float2 o; o.x = d0 * rs * gg.x + bb.x; o.y = d1 * rs * gg.y + bb.y;
    ((float2*)g_x)[row * 32 + lane] = o;
}

// ---------------- readout ----------------
__global__ void readout_kernel(const int* __restrict__ agent_nodes,
                               const float* __restrict__ Wr, const float* __restrict__ br)
{
    int i = blockIdx.x * blockDim.x + threadIdx.x;
    if (i >= NB * NA) return;
    int bi = i / NA, a = i % NA;
    int node = agent_nodes[bi];
    float s = br[a];
    #pragma unroll
    for (int h = 0; h < HDIM; h++) s += g_x[node * HDIM + h] * Wr[h * NA + a];
    g_gat[i] = s;
}

// ---------------- FC heads (fp32) ----------------
__global__ __launch_bounds__(256) void fc_kernel(
    const float* __restrict__ A, const float* __restrict__ W,
    const float* __restrict__ bias, float* __restrict__ C,
    int in_dim, int out_dim, int act)
{
    __shared__ float srow[1536];
    int row = blockIdx.x;
    for (int i = threadIdx.x; i < in_dim; i += blockDim.x)
        srow[i] = A[row * in_dim + i];
    __syncthreads();
    for (int j = threadIdx.x; j < out_dim; j += blockDim.x) {
        float s = bias ? bias[j] : 0.0f;
        for (int k = 0; k < in_dim; k++) s += srow[k] * W[k * out_dim + j];
        if (act == 1) s = tanhf(s);
        C[row * out_dim + j] = s;
    }
}

__global__ __launch_bounds__(256) void fc_concat_kernel(
    const float* __restrict__ obs, const float* __restrict__ W,
    const float* __restrict__ bias)
{
    __shared__ float srow[1536];
    int row = blockIdx.x;
    for (int i = threadIdx.x; i < NA; i += blockDim.x) srow[i] = g_gat[row * NA + i];
    for (int i = threadIdx.x; i < OBSD; i += blockDim.x) srow[NA + i] = obs[row * OBSD + i];
    __syncthreads();
    const int in_dim = NA + OBSD;
    for (int j = threadIdx.x; j < HSD; j += blockDim.x) {
        float s = bias[j];
        for (int k = 0; k < in_dim; k++) s += srow[k] * W[k * HSD + j];
        g_feat[row * HSD + j] = tanhf(s);
    }
}

__global__ void value_kernel(const float* __restrict__ Wvo, const float* __restrict__ bvo,
                             float* __restrict__ out)
{
    int bi = threadIdx.x;
    if (bi >= NB) return;
    float s = bvo[0];
    #pragma unroll
    for (int k = 0; k < VHD; k++) s += g_vh2[bi * VHD + k] * Wvo[k];
    out[NB * NOUTD + bi] = s;
}

// ---------------- launch ----------------
extern "C" void kernel_launch(void* const* d_in, const int* in_sizes, int n_in,
                              void* d_out, int out_size)
{
    const float* node_feats = (const float*)d_in[0];
    const float* obs        = (const float*)d_in[1];
    const int*   edge_src   = (const int*)d_in[2];
    const int*   edge_dst   = (const int*)d_in[3];
    const int*   agent_nodes= (const int*)d_in[4];
    const float* W_in = (const float*)d_in[5];
    const float* Wq   = (const float*)d_in[6];
    const float* Wk   = (const float*)d_in[7];
    const float* Wv   = (const float*)d_in[8];
    const float* Wo   = (const float*)d_in[9];
    const float* ln1g = (const float*)d_in[10];
    const float* ln1b = (const float*)d_in[11];
    const float* W1   = (const float*)d_in[12];
    const float* b1   = (const float*)d_in[13];
    const float* W2   = (const float*)d_in[14];
    const float* b2   = (const float*)d_in[15];
    const float* ln2g = (const float*)d_in[16];
    const float* ln2b = (const float*)d_in[17];
    const float* Wr   = (const float*)d_in[18];
    const float* br   = (const float*)d_in[19];
    const float* Wp1  = (const float*)d_in[20];
    const float* bp1  = (const float*)d_in[21];
    const float* Wp2  = (const float*)d_in[22];
    const float* bp2  = (const float*)d_in[23];
    const float* Wlog = (const float*)d_in[24];
    const float* blog = (const float*)d_in[25];
    const float* Wv1  = (const float*)d_in[26];
    const float* bv1  = (const float*)d_in[27];
    const float* Wv2  = (const float*)d_in[28];
    const float* bv2  = (const float*)d_in[29];
    const float* Wvo  = (const float*)d_in[30];
    const float* bvo  = (const float*)d_in[31];
    float* out = (float*)d_out;

    float *x, *q, *k, *v, *buf, *buf2, *hid, *feat, *feat2, *vh, *vh2;
    cudaGetSymbolAddress((void**)&x,    g_x);
    cudaGetSymbolAddress((void**)&q,    g_q);
    cudaGetSymbolAddress((void**)&k,    g_k);
    cudaGetSymbolAddress((void**)&v,    g_v);
    cudaGetSymbolAddress((void**)&buf,  g_buf);
    cudaGetSymbolAddress((void**)&buf2, g_buf2);
    cudaGetSymbolAddress((void**)&hid,  g_hid);
    cudaGetSymbolAddress((void**)&feat, g_feat);
    cudaGetSymbolAddress((void**)&feat2,g_feat2);
    cudaGetSymbolAddress((void**)&vh,   g_vh);
    cudaGetSymbolAddress((void**)&vh2,  g_vh2);

    const int MB = TOT / 128;  // 1000 row blocks

    // CSR build (reused by all 4 layers)
    zero_counts_kernel<<<(TOT + 255) / 256, 256>>>();
    count_edges_kernel<<<(NEDGE + 255) / 256, 256>>>(edge_dst);
    scan_kernel<<<1, 1024>>>();
    scatter_edges_kernel<<<(NEDGE + 255) / 256, 256>>>(edge_src, edge_dst);

    // input projection: x = node_feats @ W_in   [TOT,32]@[32,64]
    gemm_tf32_kernel<<<dim3(1, MB), 256>>>(node_feats, W_in, nullptr, x, 64, 32, 0);

    for (int l = 0; l < NLAYER; l++) {
        const float* Wq_l = Wq + l * HDIM * HDIM;
        const float* Wk_l = Wk + l * HDIM * HDIM;
        const float* Wv_l = Wv + l * HDIM * HDIM;
        const float* Wo_l = Wo + l * HDIM * HDIM;
        gemm_tf32_kernel<<<dim3(1, MB), 256>>>(x, Wq_l, nullptr, q, 64, 64, 0);
        gemm_tf32_kernel<<<dim3(1, MB), 256>>>(x, Wk_l, nullptr, k, 64, 64, 0);
        gemm_tf32_kernel<<<dim3(1, MB), 256>>>(x, Wv_l, nullptr, v, 64, 64, 0);
        gat_attn_kernel<<<TOT / 8, 256>>>();
        gemm_tf32_kernel<<<dim3(1, MB), 256>>>(buf, Wo_l, nullptr, buf2, 64, 64, 0);
        resid_ln_kernel<<<TOT / 8, 256>>>(buf2, ln1g + l * HDIM, ln1b + l * HDIM);
        gemm_tf32_kernel<<<dim3(2, MB), 256>>>(x, W1 + l * HDIM * 2 * HDIM, b1 + l * 2 * HDIM,
                                               hid, 2 * HDIM, HDIM, 1);
        gemm_tf32_kernel<<<dim3(1, MB), 256>>>(hid, W2 + l * 2 * HDIM * HDIM, b2 + l * HDIM,
                                               buf2, HDIM, 2 * HDIM, 0);
        resid_ln_kernel<<<TOT / 8, 256>>>(buf2, ln2g + l * HDIM, ln2b + l * HDIM);
    }

    // heads (fp32, small)
    readout_kernel<<<(NB * NA + 255) / 256, 256>>>(agent_nodes, Wr, br);
    fc_concat_kernel<<<NB, 256>>>(obs, Wp1, bp1);
    fc_kernel<<<NB, 256>>>(feat, Wp2, bp2, feat2, HSD, HSD, 1);
    fc_kernel<<<NB, 256>>>(feat2, Wlog, blog, out, HSD, NOUTD, 0);
    fc_kernel<<<NB, 256>>>(obs, Wv1, bv1, vh, OBSD, VHD, 1);
    fc_kernel<<<NB, 256>>>(vh, Wv2, bv2, vh2, VHD, VHD, 1);
    value_kernel<<<1, 128>>>(Wvo, bvo, out);
}